// round 13
// baseline (speedup 1.0000x reference)
#include <cuda_runtime.h>

// NCC2D: -mean( cross^2 / (I_var*J_var + 1e-5) ), 9x9 zero-padded box sums.
// cross = IJ - I*J/81 ; I_var = I2 - I^2/81 ; J_var = J2 - J^2/81.
//
// R10 structure (bench 30.8us: 22x32 blocks, TPB=128, 4 cols/thread,
// lb(128,5), guard-free interior strips, double-buffered smem V exchange)
// + software pipelining:
//   - new-row loads (a1,b1) for iteration it+1 are issued BEFORE EMIT
//     (clamped row, branch-free) so EMIT's ~100 instrs hide their latency;
//     ptxas cannot hoist loads across the barrier itself.
//   - VUPDATE split into VADD (prefetched data, ready) + VSUB (old rows
//     loaded at loop top; VADD's 20 instrs cover their L1-hit latency).
//   - warm-up uses VADD only (no zero-subtract busywork).
//   Block partial -> double atomic; last block finalizes + resets.

#define BW   512
#define BH   512
#define NB   32
#define ROWS 24
#define TPB  128
#define STRIPS 22                    // 21 full strips of 24 + one of 8
#define NBLOCKS (STRIPS * NB)        // 704

__device__ double       g_acc;   // zero-init at load; reset by last block
__device__ unsigned int g_cnt;

__global__ __launch_bounds__(TPB, 5) void ncc_main_k(const float* __restrict__ gI,
                                                     const float* __restrict__ gJ,
                                                     float* __restrict__ out) {
    __shared__ float4 sV[2][5][TPB];     // double-buffered V exchange: 20480 B
    __shared__ float  wsum[TPB / 32];

    const int t    = threadIdx.x;
    const int lane = t & 31;
    const int r0   = blockIdx.x * ROWS;
    const size_t img = (size_t)blockIdx.y * ((size_t)BH * BW);
    const float4 z = make_float4(0.f, 0.f, 0.f, 0.f);
    const float inv81 = 1.0f / 81.0f;

    const float4* bI = (const float4*)(gI + img) + t;   // stride BW/4 per row
    const float4* bJ = (const float4*)(gJ + img) + t;

    float vI[4]  = {0.f, 0.f, 0.f, 0.f};
    float vJ[4]  = {0.f, 0.f, 0.f, 0.f};
    float vI2[4] = {0.f, 0.f, 0.f, 0.f};
    float vJ2[4] = {0.f, 0.f, 0.f, 0.f};
    float vIJ[4] = {0.f, 0.f, 0.f, 0.f};
    float acc = 0.f;

// Add a new row into the vertical running sums.
#define VADD(A1, B1)                                                           \
    {                                                                          \
        const float an[4] = {(A1).x, (A1).y, (A1).z, (A1).w};                  \
        const float bn[4] = {(B1).x, (B1).y, (B1).z, (B1).w};                  \
        _Pragma("unroll")                                                      \
        for (int c = 0; c < 4; ++c) {                                          \
            vI[c] += an[c];                                                    \
            vJ[c] += bn[c];                                                    \
            vI2[c] = fmaf(an[c], an[c], vI2[c]);                               \
            vJ2[c] = fmaf(bn[c], bn[c], vJ2[c]);                               \
            vIJ[c] = fmaf(an[c], bn[c], vIJ[c]);                               \
        }                                                                      \
    }

// Subtract an old row from the vertical running sums.
#define VSUB(AO, BO)                                                           \
    {                                                                          \
        const float ap[4] = {(AO).x, (AO).y, (AO).z, (AO).w};                  \
        const float bp[4] = {(BO).x, (BO).y, (BO).z, (BO).w};                  \
        _Pragma("unroll")                                                      \
        for (int c = 0; c < 4; ++c) {                                          \
            vI[c] -= ap[c];                                                    \
            vJ[c] -= bp[c];                                                    \
            vI2[c] = fmaf(-ap[c], ap[c], vI2[c]);                              \
            vJ2[c] = fmaf(-bp[c], bp[c], vJ2[c]);                              \
            vIJ[c] = fmaf(-ap[c], bp[c], vIJ[c]);                              \
        }                                                                      \
    }

#define DO_WIN(P, VA)                                                          \
    {                                                                          \
        float4 L = (t > 0)       ? sV[buf][P][t - 1] : z;                      \
        float4 R = (t < TPB - 1) ? sV[buf][P][t + 1] : z;                      \
        float v0 = L.x, v1 = L.y, v2 = L.z, v3 = L.w;                          \
        float v4 = VA[0], v5 = VA[1], v6 = VA[2], v7 = VA[3];                  \
        float v8 = R.x, v9 = R.y, v10 = R.z, v11 = R.w;                        \
        float w = ((v0 + v1) + (v2 + v3)) + ((v4 + v5) + (v6 + v7)) + v8;      \
        box[P][0] = w;                                                         \
        box[P][1] = w = w - v0 + v9;                                           \
        box[P][2] = w = w - v1 + v10;                                          \
        box[P][3] =     w - v2 + v11;                                          \
    }

// Emit one output row via smem exchange buffer BUF (0/1).
#define EMIT(BUF)                                                              \
    {                                                                          \
        const int buf = (BUF);                                                 \
        sV[buf][0][t] = make_float4(vI[0],  vI[1],  vI[2],  vI[3]);            \
        sV[buf][1][t] = make_float4(vJ[0],  vJ[1],  vJ[2],  vJ[3]);            \
        sV[buf][2][t] = make_float4(vI2[0], vI2[1], vI2[2], vI2[3]);           \
        sV[buf][3][t] = make_float4(vJ2[0], vJ2[1], vJ2[2], vJ2[3]);           \
        sV[buf][4][t] = make_float4(vIJ[0], vIJ[1], vIJ[2], vIJ[3]);           \
        __syncthreads();                                                       \
        float box[5][4];                                                       \
        DO_WIN(0, vI)                                                          \
        DO_WIN(1, vJ)                                                          \
        DO_WIN(2, vI2)                                                         \
        DO_WIN(3, vJ2)                                                         \
        DO_WIN(4, vIJ)                                                         \
        _Pragma("unroll")                                                      \
        for (int c = 0; c < 4; ++c) {                                          \
            float sI = box[0][c], sJ = box[1][c];                              \
            float cross = fmaf(sI * sJ, -inv81, box[4][c]);                    \
            float Iv    = fmaf(sI * sI, -inv81, box[2][c]);                    \
            float Jv    = fmaf(sJ * sJ, -inv81, box[3][c]);                    \
            float den   = fmaf(Iv, Jv, 1e-5f);                                 \
            acc += __fdividef(cross * cross, den);                             \
        }                                                                      \
    }

    if (r0 >= ROWS && r0 + ROWS + 4 <= BH) {
        // ---------- interior strip (20 of 22): zero range checks ----------
        // Warm-up: add rows r0-4 .. r0+3 (all in-range), no subtract, no emit.
#pragma unroll
        for (int it = 0; it < 8; ++it) {
            const int rn = r0 - 4 + it;
            float4 wa = __ldg(bI + (size_t)rn * (BW / 4));
            float4 wb = __ldg(bJ + (size_t)rn * (BW / 4));
            VADD(wa, wb)
        }
        // it = 8: window full, first emit; prefetch it=9's new rows first.
        float4 a1, b1;
        {
            float4 wa = __ldg(bI + (size_t)(r0 + 4) * (BW / 4));
            float4 wb = __ldg(bJ + (size_t)(r0 + 4) * (BW / 4));
            VADD(wa, wb)
            a1 = __ldg(bI + (size_t)(r0 + 5) * (BW / 4));   // prefetch it=9
            b1 = __ldg(bJ + (size_t)(r0 + 5) * (BW / 4));
            EMIT(0)
        }
        // Steady: it = 9..ROWS+7 — all rows provably in-range.
#pragma unroll 2
        for (int it = 9; it < ROWS + 8; ++it) {
            const int rn = r0 - 4 + it;
            const int ro = rn - 9;
            float4 ao = __ldg(bI + (size_t)ro * (BW / 4));   // old rows in flight
            float4 bo = __ldg(bJ + (size_t)ro * (BW / 4));
            VADD(a1, b1)                                     // prefetched: ready
            VSUB(ao, bo)                                     // covered by VADD
            const int rp = min(rn + 1, BH - 1);              // clamped prefetch
            a1 = __ldg(bI + (size_t)rp * (BW / 4));          // hidden by EMIT
            b1 = __ldg(bJ + (size_t)rp * (BW / 4));
            EMIT(it & 1)
        }
    } else {
        // ---------- edge strips: guarded generic loop ----------
        const int rows_eff = min(ROWS, BH - r0);
        const int iters = rows_eff + 8;
#pragma unroll 2
        for (int it = 0; it < iters; ++it) {
            const int rn = r0 - 4 + it;
            const int ro = rn - 9;
            if (rn >= 0 && rn < BH) {
                float4 wa = __ldg(bI + (size_t)rn * (BW / 4));
                float4 wb = __ldg(bJ + (size_t)rn * (BW / 4));
                VADD(wa, wb)
            }
            if (it >= 9 && ro >= 0) {   // only rows actually added earlier
                float4 wa = __ldg(bI + (size_t)ro * (BW / 4));
                float4 wb = __ldg(bJ + (size_t)ro * (BW / 4));
                VSUB(wa, wb)
            }
            if (it >= 8) EMIT(it & 1)
        }
    }
#undef DO_WIN
#undef EMIT
#undef VSUB
#undef VADD

    // Block reduction -> global double atomic; last block finalizes + resets.
#pragma unroll
    for (int o = 16; o; o >>= 1) acc += __shfl_xor_sync(0xffffffffu, acc, o);
    if (lane == 0) wsum[t >> 5] = acc;
    __syncthreads();
    if (t == 0) {
        float bs = 0.f;
#pragma unroll
        for (int w = 0; w < TPB / 32; ++w) bs += wsum[w];
        atomicAdd(&g_acc, (double)bs);
        __threadfence();
        unsigned int done = atomicAdd(&g_cnt, 1u);
        if (done == NBLOCKS - 1) {
            __threadfence();
            double v = *((volatile double*)&g_acc);
            out[0] = (float)(-v * (1.0 / (double)((long long)NB * BH * BW)));
            g_acc = 0.0;          // reset for next graph replay
            g_cnt = 0u;
        }
    }
}

extern "C" void kernel_launch(void* const* d_in, const int* in_sizes, int n_in,
                              void* d_out, int out_size) {
    const float* I = (const float*)d_in[0];
    const float* J = (const float*)d_in[1];
    float* out = (float*)d_out;

    dim3 grid(STRIPS, NB);   // (22, 32) = 704 blocks, single wave at 5/SM
    ncc_main_k<<<grid, TPB>>>(I, J, out);
}